// round 12
// baseline (speedup 1.0000x reference)
#include <cuda_runtime.h>
#include <math.h>

#define NX 64
#define ME 40
#define NITER 25
#define NBLK 210   /* 20*21/2 2x2-blocks of the 40x40 lower triangle */
#define SPN 824    /* packed lower triangle (820) padded */

// Batch-invariant products P[k][blk][m] = A[r_m][k]*A[c_m][k]  (430KB, L2-hot)
__device__ double g_P[NX * NBLK * 4];

struct __align__(16) Smem {
  double A[ME][NX + 2];
  double Sp[2][SPN];          // packed LDL factors, 2 items
  double invd[2][ME];
  double p[2][NX], x[2][NX], s[2][NX], z[2][NX];
  double iw[2][NX], wv[2][NX], cv[2][NX], rsv[2][NX], rhx[2][NX], vv[2][NX];
  double dx[2][NX], dsv[2][NX], dzv[2][NX];
  double uv[NX];
  double y[2][ME], dy[2][ME], rhy[2][ME], bv[ME];
  double red[8];
  double mu[2], alpha[2];
  int is64;
};

__device__ __forceinline__ double piv_floor(double d) {
  return (d > 1e-280) ? d : 1e-280;   // catches NaN / nonpositive too
}

__global__ void __launch_bounds__(256) prep_kernel(const void* __restrict__ gA) {
  __shared__ int s_is64;
  if (threadIdx.x == 0) {
    const double* ad = (const double*)gA;
    int cnt = 0;
    #pragma unroll
    for (int i = 0; i < 16; ++i) {
      double v = ad[i];
      if (v > 1e-3 && v < 1.0) ++cnt;
    }
    s_is64 = (cnt >= 12) ? 1 : 0;
  }
  __syncthreads();
  const double* A64 = (const double*)gA; const float* A32 = (const float*)gA;
  int idx = blockIdx.x * 256 + threadIdx.x;          // over 64*210*4
  if (idx >= NX * NBLK * 4) return;
  int m   = idx & 3;
  int blk = (idx >> 2) % NBLK;
  int k   = idx / (NBLK * 4);
  int br = (int)((sqrtf(8.0f * (float)blk + 1.0f) - 1.0f) * 0.5f);
  while ((br + 1) * (br + 2) / 2 <= blk) ++br;
  while (br * (br + 1) / 2 > blk) --br;
  int bc = blk - br * (br + 1) / 2;
  int r = 2 * br + (m >> 1), c = 2 * bc + (m & 1);
  double ar = s_is64 ? A64[r * NX + k] : (double)A32[r * NX + k];
  double ac = s_is64 ? A64[c * NX + k] : (double)A32[c * NX + k];
  g_P[idx] = ar * ac;
}

__global__ void __launch_bounds__(256, 3) qp_ipm_kernel(
    const float* __restrict__ puz, const void* __restrict__ gA,
    const void* __restrict__ glz, const void* __restrict__ gu,
    float* __restrict__ out, int nbatch)
{
  extern __shared__ double shraw[];
  Smem* sh = reinterpret_cast<Smem*>(shraw);
  const int t = threadIdx.x, lane = t & 31, wid = t >> 5;
  const unsigned F = 0xffffffffu;
  const int i0 = 2 * blockIdx.x;
  const int i1 = (i0 + 1 < nbatch) ? i0 + 1 : i0;

  // ---- dtype detection: fp64 inputs may be delivered as fp32 buffers ----
  if (t == 0) {
    const double* ad = (const double*)gA;
    int cnt = 0;
    #pragma unroll
    for (int i = 0; i < 16; ++i) {
      double v = ad[i];
      if (v > 1e-3 && v < 1.0) ++cnt;
    }
    sh->is64 = (cnt >= 12) ? 1 : 0;
  }
  __syncthreads();
  const int is64 = sh->is64;
  const double* A64 = (const double*)gA;  const float* A32 = (const float*)gA;
  const double* L64 = (const double*)glz; const float* L32 = (const float*)glz;
  const double* U64 = (const double*)gu;  const float* U32 = (const float*)gu;

  // ---- load A, p(2 items), init state ----
  for (int i = t; i < ME * NX; i += 256)
    sh->A[i >> 6][i & 63] = is64 ? A64[i] : (double)A32[i];
  if (t < NX) {
    sh->uv[t] = is64 ? U64[t] : (double)U32[t];
    double lzv = is64 ? L64[t] : (double)L32[t];
    sh->vv[0][t] = exp(lzv);   // scratch for b
  }
  if (t < 128) {
    int it = t >> 6, k = t & 63;
    int item = it ? i1 : i0;
    sh->p[it][k] = -(double)puz[item * NX + k];
    sh->x[it][k] = 0.0; sh->s[it][k] = 1.0; sh->z[it][k] = 1.0;
  }
  if (t < 2 * ME) { int it = t / ME, a = t % ME; sh->y[it][a] = 0.0; }
  __syncthreads();

  // ---- b = A @ exp(log_z0) (shared by both items) ----
  for (int a = wid; a < ME; a += 8) {
    double acc = 0.0;
    for (int k = lane; k < NX; k += 32) acc += sh->A[a][k] * sh->vv[0][k];
    for (int o = 16; o; o >>= 1) acc += __shfl_down_sync(F, acc, o);
    if (lane == 0) sh->bv[a] = acc;
  }

  // ---- static 2x2 block assignment (1 block/thread, 210 active) ----
  const bool act = (t < NBLK);
  int br = 0, bc = 0;
  {
    int e = act ? t : 0;
    int a = (int)((sqrtf(8.0f * (float)e + 1.0f) - 1.0f) * 0.5f);
    while ((a + 1) * (a + 2) / 2 <= e) ++a;
    while (a * (a + 1) / 2 > e) --a;
    br = a; bc = e - a * (a + 1) / 2;
  }
  const int r0 = 2 * br, r1 = r0 + 1, c0 = 2 * bc, c1 = c0 + 1;
  const int pb0 = r0 * (r0 + 1) / 2, pb1 = r1 * (r1 + 1) / 2;
  const int cb0 = c0 * (c0 + 1) / 2, cb1 = c1 * (c1 + 1) / 2;
  const double4* Pp = reinterpret_cast<const double4*>(g_P) + t;  // [k][blk]
  double* Sp0 = sh->Sp[0];
  double* Sp1 = sh->Sp[1];
  __syncthreads();

  // ==================== 25 IPM iterations ====================
  for (int itn = 0; itn < NITER; ++itn) {
    // mu (warps 0,1 -> items 0,1) ; aty = A^T y (2 threads/k/item) into dx
    if (wid < 2) {
      double v = sh->s[wid][lane] * sh->z[wid][lane]
               + sh->s[wid][lane + 32] * sh->z[wid][lane + 32];
      for (int o = 16; o; o >>= 1) v += __shfl_down_sync(F, v, o);
      if (lane == 0) sh->mu[wid] = v * (1.0 / 64.0);
    }
    {
      int it = t >> 7, tt = t & 127, k = tt >> 1, j2 = tt & 1;
      double acc = 0.0;
      #pragma unroll
      for (int a = j2; a < ME; a += 2) acc += sh->A[a][k] * sh->y[it][a];
      acc += __shfl_xor_sync(F, acc, 1);
      if (j2 == 0) sh->dx[it][k] = acc;
    }
    __syncthreads();

    // per-element residuals / scalings; vv = x + iw*rhs_x
    if (t < 128) {
      int it = t >> 6, k = t & 63;
      double mu = sh->mu[it];
      double sv = sh->s[it][k], zv = sh->z[it][k];
      double inv_s = 1.0 / sv, inv_z = 1.0 / zv;
      double rs  = sv - sh->x[it][k] - sh->uv[k];      // G x + s - u, G=-I
      double w   = zv * inv_s;
      double iwv = sv * inv_z;                          // s/z
      double c   = (0.1 * mu - zv * sv + zv * rs) * inv_s;
      double rd  = sh->p[it][k] + sh->dx[it][k] - zv;   // Qx=0, G^T z=-z
      double rhx = c - rd;                              // rhs_x = -(rd + G^T c)
      sh->rsv[it][k] = rs; sh->wv[it][k] = w; sh->iw[it][k] = iwv;
      sh->cv[it][k] = c;  sh->rhx[it][k] = rhx;
      sh->vv[it][k] = sh->x[it][k] + iwv * rhx;
    }
    __syncthreads();

    // rhy = A @ vv - b  (warps 0-3 item0, warps 4-7 item1)
    {
      int it = wid >> 2, w4 = wid & 3;
      for (int a = w4; a < ME; a += 4) {
        double acc = 0.0;
        for (int k = lane; k < NX; k += 32) acc += sh->A[a][k] * sh->vv[it][k];
        for (int o = 16; o; o >>= 1) acc += __shfl_down_sync(F, acc, o);
        if (lane == 0) sh->rhy[it][a] = acc - sh->bv[a];
      }
    }

    // S (2x2 blocks, both items) = sum_k P[k]*iw[it][k]
    double va000 = 0.0, va001 = 0.0, va010 = 0.0, va011 = 0.0;
    double va100 = 0.0, va101 = 0.0, va110 = 0.0, va111 = 0.0;
    if (act) {
      #pragma unroll 4
      for (int k = 0; k < NX; ++k) {
        double4 pa = Pp[k * NBLK];
        double w0 = sh->iw[0][k], w1 = sh->iw[1][k];
        va000 += pa.x * w0; va001 += pa.y * w0;
        va010 += pa.z * w0; va011 += pa.w * w0;
        va100 += pa.x * w1; va101 += pa.y * w1;
        va110 += pa.z * w1; va111 += pa.w * w1;
      }
      if (c0 == 0) {
        Sp0[pb0] = va000; Sp0[pb1] = va010;
        Sp1[pb0] = va100; Sp1[pb1] = va110;
        if (br == 0) {
          sh->invd[0][0] = 1.0 / piv_floor(va000);
          sh->invd[1][0] = 1.0 / piv_floor(va100);
        }
      }
    }
    __syncthreads();

    // ---- LDL^T for both items: 2x2 register blocks, 1 barrier/column ----
    for (int j = 0; j < ME - 1; ++j) {
      const int jn = j + 1;
      if (act && c1 > j) {
        const double g0 = sh->invd[0][j], g1 = sh->invd[1][j];
        const double sr0a = Sp0[pb0 + j], sr1a = Sp0[pb1 + j];
        const double sr0b = Sp1[pb0 + j], sr1b = Sp1[pb1 + j];
        if (c0 > j) {
          double tc0a = Sp0[cb0 + j] * g0;
          double tc0b = Sp1[cb0 + j] * g1;
          va000 -= sr0a * tc0a; va010 -= sr1a * tc0a;
          va100 -= sr0b * tc0b; va110 -= sr1b * tc0b;
        }
        double tc1a = Sp0[cb1 + j] * g0;
        double tc1b = Sp1[cb1 + j] * g1;
        va001 -= sr0a * tc1a; va011 -= sr1a * tc1a;
        va101 -= sr0b * tc1b; va111 -= sr1b * tc1b;
        if (c0 == jn) {
          Sp0[pb0 + c0] = va000; Sp0[pb1 + c0] = va010;
          Sp1[pb0 + c0] = va100; Sp1[pb1 + c0] = va110;
          if (br == bc) {
            sh->invd[0][c0] = 1.0 / piv_floor(va000);
            sh->invd[1][c0] = 1.0 / piv_floor(va100);
          }
        } else if (c1 == jn) {
          if (br > bc) { Sp0[pb0 + c1] = va001; Sp1[pb0 + c1] = va101; }
          Sp0[pb1 + c1] = va011; Sp1[pb1 + c1] = va111;
          if (br == bc) {
            sh->invd[0][c1] = 1.0 / piv_floor(va011);
            sh->invd[1][c1] = 1.0 / piv_floor(va111);
          }
        }
      }
      __syncthreads();
    }

    // ---- triangular solves: warp 0 -> item 0, warp 1 -> item 1 ----
    if (wid < 2) {
      const int it = wid;
      double* Sp = sh->Sp[it];
      const int rA = lane, rB = lane + 32;
      const int bA = rA * (rA + 1) / 2, bB = rB * (rB + 1) / 2;
      double r0v = (rA < ME) ? sh->rhy[it][rA] : 0.0;
      double r1v = (rB < ME) ? sh->rhy[it][rB] : 0.0;
      // forward: L t = rhy  (L[i][j] = Sp[i][j]*invd[j])
      #pragma unroll 1
      for (int j = 0; j < ME; ++j) {
        double tj = (j < 32) ? __shfl_sync(F, r0v, j)
                             : __shfl_sync(F, r1v, j - 32);
        double f = tj * sh->invd[it][j];
        if (rA > j && rA < ME) r0v -= Sp[bA + j] * f;
        if (rB > j && rB < ME) r1v -= Sp[bB + j] * f;
      }
      // u = D^{-1} t
      double u0 = (rA < ME) ? r0v * sh->invd[it][rA] : 0.0;
      double u1 = (rB < ME) ? r1v * sh->invd[it][rB] : 0.0;
      // backward: L^T dy = u (column-oriented)
      double a0 = 0.0, a1 = 0.0;
      #pragma unroll 1
      for (int c = ME - 1; c >= 0; --c) {
        const int cb = c * (c + 1) / 2;
        double uc, ac;
        if (c < 32) { uc = __shfl_sync(F, u0, c);      ac = __shfl_sync(F, a0, c); }
        else        { uc = __shfl_sync(F, u1, c - 32); ac = __shfl_sync(F, a1, c - 32); }
        double dyc = uc - sh->invd[it][c] * ac;
        if (rA < c) a0 += Sp[cb + rA] * dyc;
        if (rB < c) a1 += Sp[cb + rB] * dyc;
        if (lane == 0) sh->dy[it][c] = dyc;
      }
    }
    __syncthreads();

    // dx = (rhs_x - A^T dy) * iw ; ds = dx - rs ; dz = c - w*dx
    {
      int it = t >> 7, tt = t & 127, k = tt >> 1, j2 = tt & 1;
      double acc = 0.0;
      #pragma unroll
      for (int a = j2; a < ME; a += 2) acc += sh->A[a][k] * sh->dy[it][a];
      acc += __shfl_xor_sync(F, acc, 1);
      if (j2 == 0) {
        double dxk = (sh->rhx[it][k] - acc) * sh->iw[it][k];
        sh->dx[it][k]  = dxk;
        sh->dsv[it][k] = dxk - sh->rsv[it][k];
        sh->dzv[it][k] = sh->cv[it][k] - sh->wv[it][k] * dxk;
      }
    }
    __syncthreads();

    // alpha = min(1, 0.99*min ratios): warps 0-3 item0, 4-7 item1
    {
      int it = t >> 7, tt = t & 127, k = tt & 63, ty = tt >> 6;
      double v  = ty ? sh->z[it][k]   : sh->s[it][k];
      double dv = ty ? sh->dzv[it][k] : sh->dsv[it][k];
      double ratio = (dv < 0.0) ? (v / (-dv)) : 1e300;
      if (!isfinite(dv)) ratio = 0.0;
      for (int o = 16; o; o >>= 1) ratio = fmin(ratio, __shfl_xor_sync(F, ratio, o));
      if (lane == 0) sh->red[wid] = ratio;
    }
    __syncthreads();
    if (t == 0) {
      double m = fmin(fmin(sh->red[0], sh->red[1]), fmin(sh->red[2], sh->red[3]));
      sh->alpha[0] = fmin(1.0, 0.99 * m);
    }
    if (t == 32) {
      double m = fmin(fmin(sh->red[4], sh->red[5]), fmin(sh->red[6], sh->red[7]));
      sh->alpha[1] = fmin(1.0, 0.99 * m);
    }
    __syncthreads();
    if (t < 128) {
      int it = t >> 6, k = t & 63;
      double alpha = sh->alpha[it];
      sh->x[it][k] += alpha * sh->dx[it][k];
      sh->s[it][k] += alpha * sh->dsv[it][k];
      sh->z[it][k] += alpha * sh->dzv[it][k];
    } else if (t < 128 + 2 * ME) {
      int tt = t - 128, it = tt / ME, a = tt % ME;
      sh->y[it][a] += sh->alpha[it] * sh->dy[it][a];
    }
    __syncthreads();
  }

  if (t < 128) {
    int it = t >> 6, k = t & 63;
    int item = it ? i1 : i0;
    double v = sh->x[it][k];
    out[(size_t)item * NX + k] = isfinite(v) ? (float)v : 1e6f;
  }
}

extern "C" void kernel_launch(void* const* d_in, const int* in_sizes, int n_in,
                              void* d_out, int out_size) {
  const float* puz = nullptr;
  const void*  A   = nullptr;
  const void*  lz  = nullptr;
  const void*  u   = nullptr;
  int npuz = 0;
  for (int i = 0; i < n_in; ++i) {
    int sz = in_sizes[i];
    if (sz == ME * NX) { A = d_in[i]; }
    else if (sz == NX) {
      if (!lz) lz = d_in[i];
      else     u  = d_in[i];
    }
    else if (sz % NX == 0 && sz != NX * NX) {
      puz = (const float*)d_in[i]; npuz = sz;
    }
  }
  if (!puz || !A || !lz) {             // positional fallback (setup_inputs order)
    puz = (const float*)d_in[0]; npuz = in_sizes[0];
    A   = d_in[1];
    lz  = d_in[2];
    u   = d_in[5];
  }
  if (!u) u = lz;
  float* out = (float*)d_out;

  int nbatch = npuz / NX;
  int smem = (int)sizeof(Smem);

  prep_kernel<<<(NX * NBLK * 4 + 255) / 256, 256>>>(A);

  cudaFuncSetAttribute(qp_ipm_kernel,
                       cudaFuncAttributeMaxDynamicSharedMemorySize, smem);
  qp_ipm_kernel<<<(nbatch + 1) / 2, 256, smem>>>(puz, A, lz, u, out, nbatch);
}